// round 1
// baseline (speedup 1.0000x reference)
#include <cuda_runtime.h>
#include <math.h>

#define ND 100000
#define NP 100000
#define EE 800000

// ---------------- scratch (__device__ globals; no allocations) ----------------
__device__ float g_hd[ND * 128];      // relu(x_drug @ W_in_d + b)
__device__ float g_hp[NP * 128];      // relu(x_prot @ W_in_p + b)
__device__ float g_fs_dp[ND * 128];   // h_d @ W_dp   (src feats, etype dp)
__device__ float g_fd_dp[NP * 128];   // h_p @ W_dp   (dst feats, etype dp)
__device__ float g_fs_pd[NP * 128];   // h_p @ W_pd
__device__ float g_fd_pd[ND * 128];   // h_d @ W_pd
__device__ float g_agg_p[NP * 128];   // GAT output for proteins (init = bias_dp)
__device__ float g_agg_d[ND * 128];   // GAT output for drugs    (init = bias_pd)
__device__ float g_el_dp[ND * 4];
__device__ float g_er_dp[NP * 4];
__device__ float g_el_pd[NP * 4];
__device__ float g_er_pd[ND * 4];
__device__ float g_s_p[NP * 4];       // softmax denominators
__device__ float g_s_d[ND * 4];
__device__ float g_ex_dp[EE * 4];     // exp(e) per edge per head
__device__ float g_ex_pd[EE * 4];

// ---------------- helpers ----------------
__device__ __forceinline__ void red_add_v4(float* addr, float4 v) {
    asm volatile("red.global.add.v4.f32 [%0], {%1,%2,%3,%4};"
                 :: "l"(addr), "f"(v.x), "f"(v.y), "f"(v.z), "f"(v.w)
                 : "memory");
}

__device__ __forceinline__ float lrelu_exp(float v) {
    // leaky_relu(v, 0.2) then exp. (Softmax max-shift omitted: shift-invariant,
    // and |e| is O(1) with these weight scales, so exp is safe.)
    return expf(v > 0.f ? v : 0.2f * v);
}

// ---------------- GEMM: C[n,128] = A[n,128] @ B[128,128] (+bias, +relu) ----------------
// 128x128 tile, K=128 fully resident in smem, 256 threads, 8x8 register blocking.
#define AS_STRIDE 132               // padded to kill A-row bank conflicts
#define GEMM_SMEM ((128 * AS_STRIDE + 128 * 128) * 4)

__global__ void __launch_bounds__(256, 1)
gemm128(const float* __restrict__ A, const float* __restrict__ B,
        const float* __restrict__ bias, float* __restrict__ C,
        int n, int relu_flag)
{
    extern __shared__ float sm[];
    float* As = sm;                   // [128][AS_STRIDE]
    float* Bs = sm + 128 * AS_STRIDE; // [128][128]

    const int tid = threadIdx.x;
    const int bbase = blockIdx.x * 128;

    // load A tile (zero-pad rows beyond n)
    #pragma unroll
    for (int t = tid; t < 128 * 32; t += 256) {
        int r = t >> 5, c4 = (t & 31) << 2;
        int row = bbase + r;
        float4 v = make_float4(0.f, 0.f, 0.f, 0.f);
        if (row < n) v = *(const float4*)(A + (size_t)row * 128 + c4);
        *(float4*)(As + r * AS_STRIDE + c4) = v;
    }
    // load B (full 128x128)
    #pragma unroll
    for (int t = tid; t < 128 * 32; t += 256) {
        int k = t >> 5, c4 = (t & 31) << 2;
        *(float4*)(Bs + k * 128 + c4) = *(const float4*)(B + k * 128 + c4);
    }
    __syncthreads();

    const int ty = tid >> 4;   // 0..15 -> rows ty + 16*i
    const int tx = tid & 15;   // 0..15 -> cols tx*8 + j

    float acc[8][8];
    #pragma unroll
    for (int i = 0; i < 8; i++)
        #pragma unroll
        for (int j = 0; j < 8; j++) acc[i][j] = 0.f;

    #pragma unroll 2
    for (int kk = 0; kk < 128; kk += 4) {
        float4 a[8];
        #pragma unroll
        for (int i = 0; i < 8; i++)
            a[i] = *(const float4*)(As + (ty + 16 * i) * AS_STRIDE + kk);
        #pragma unroll
        for (int q = 0; q < 4; q++) {
            float4 b0 = *(const float4*)(Bs + (kk + q) * 128 + tx * 8);
            float4 b1 = *(const float4*)(Bs + (kk + q) * 128 + tx * 8 + 4);
            #pragma unroll
            for (int i = 0; i < 8; i++) {
                float av = (q == 0) ? a[i].x : (q == 1) ? a[i].y : (q == 2) ? a[i].z : a[i].w;
                acc[i][0] += av * b0.x; acc[i][1] += av * b0.y;
                acc[i][2] += av * b0.z; acc[i][3] += av * b0.w;
                acc[i][4] += av * b1.x; acc[i][5] += av * b1.y;
                acc[i][6] += av * b1.z; acc[i][7] += av * b1.w;
            }
        }
    }

    float bv[8];
    #pragma unroll
    for (int j = 0; j < 8; j++) bv[j] = bias ? bias[tx * 8 + j] : 0.f;

    #pragma unroll
    for (int i = 0; i < 8; i++) {
        int row = bbase + ty + 16 * i;
        if (row >= n) continue;
        #pragma unroll
        for (int j = 0; j < 8; j++) {
            float v = acc[i][j] + bv[j];
            if (relu_flag) v = fmaxf(v, 0.f);
            acc[i][j] = v;
        }
        float4 o0 = make_float4(acc[i][0], acc[i][1], acc[i][2], acc[i][3]);
        float4 o1 = make_float4(acc[i][4], acc[i][5], acc[i][6], acc[i][7]);
        *(float4*)(C + (size_t)row * 128 + tx * 8) = o0;
        *(float4*)(C + (size_t)row * 128 + tx * 8 + 4) = o1;
    }
}

// ---------------- per-head dot: out[n][h] = sum_d F[n][h*32+d] * attn[h][d] ----------------
// warp per node; 8 lanes per head, float4 each, shfl tree reduce.
__global__ void headdot(const float* __restrict__ F, const float* __restrict__ attn,
                        float* __restrict__ out, int n)
{
    int gw = (int)((blockIdx.x * (size_t)blockDim.x + threadIdx.x) >> 5);
    int lane = threadIdx.x & 31;
    if (gw >= n) return;
    int head = lane >> 3, part = lane & 7;
    float4 f = ((const float4*)F)[(size_t)gw * 32 + lane];
    float4 av = ((const float4*)attn)[head * 8 + part];
    float v = f.x * av.x + f.y * av.y + f.z * av.z + f.w * av.w;
    v += __shfl_down_sync(0xffffffffu, v, 4);
    v += __shfl_down_sync(0xffffffffu, v, 2);
    v += __shfl_down_sync(0xffffffffu, v, 1);
    if (part == 0) out[gw * 4 + head] = v;
}

// ---------------- init: agg = broadcast(bias), ssum = 0 ----------------
__global__ void init_agg(float* __restrict__ agg, const float* __restrict__ bias,
                         float* __restrict__ ssum, int n)
{
    size_t i = blockIdx.x * (size_t)blockDim.x + threadIdx.x;
    if (i < (size_t)n * 128) agg[i] = bias[i & 127];
    if (i < (size_t)n * 4) ssum[i] = 0.f;
}

// ---------------- edge pass 1: exp(leaky(el[src]+er[dst])), accumulate denom ----------------
__global__ void edge_pass1(const int* __restrict__ src, const int* __restrict__ dst,
                           const float* __restrict__ el, const float* __restrict__ er,
                           float* __restrict__ exb, float* __restrict__ ssum, int ne)
{
    int e = blockIdx.x * blockDim.x + threadIdx.x;
    if (e >= ne) return;
    int s = src[e], d = dst[e];
    float4 a = ((const float4*)el)[s];
    float4 b = ((const float4*)er)[d];
    float4 x;
    x.x = lrelu_exp(a.x + b.x);
    x.y = lrelu_exp(a.y + b.y);
    x.z = lrelu_exp(a.z + b.z);
    x.w = lrelu_exp(a.w + b.w);
    ((float4*)exb)[e] = x;
    red_add_v4(ssum + (size_t)d * 4, x);
}

// ---------------- edge pass 2: agg[dst] += (ex/s[dst]) * fs[src] ----------------
// warp per edge, lane owns 4 contiguous feats (head = lane/8).
__global__ void edge_pass2(const int* __restrict__ src, const int* __restrict__ dst,
                           const float* __restrict__ exb, const float* __restrict__ ssum,
                           const float* __restrict__ fs, float* __restrict__ agg, int ne)
{
    int w = (int)((blockIdx.x * (size_t)blockDim.x + threadIdx.x) >> 5);
    int lane = threadIdx.x & 31;
    if (w >= ne) return;
    int s = src[w], d = dst[w];
    int head = lane >> 3;
    float a = exb[(size_t)w * 4 + head] / ssum[(size_t)d * 4 + head];
    float4 f = ((const float4*)fs)[(size_t)s * 32 + lane];
    float4 m = make_float4(a * f.x, a * f.y, a * f.z, a * f.w);
    red_add_v4(agg + (size_t)d * 128 + lane * 4, m);
}

// ---------------- launch ----------------
extern "C" void kernel_launch(void* const* d_in, const int* in_sizes, int n_in,
                              void* d_out, int out_size)
{
    const float* x_drug  = (const float*)d_in[0];
    const float* x_prot  = (const float*)d_in[1];
    const int*   src_dp  = (const int*)d_in[2];
    const int*   dst_dp  = (const int*)d_in[3];
    const int*   src_pd  = (const int*)d_in[4];
    const int*   dst_pd  = (const int*)d_in[5];
    const float* W_in_d  = (const float*)d_in[6];
    const float* b_in_d  = (const float*)d_in[7];
    const float* W_in_p  = (const float*)d_in[8];
    const float* b_in_p  = (const float*)d_in[9];
    const float* W_dp    = (const float*)d_in[10];
    const float* al_dp   = (const float*)d_in[11];
    const float* ar_dp   = (const float*)d_in[12];
    const float* bias_dp = (const float*)d_in[13];
    const float* W_pd    = (const float*)d_in[14];
    const float* al_pd   = (const float*)d_in[15];
    const float* ar_pd   = (const float*)d_in[16];
    const float* bias_pd = (const float*)d_in[17];
    const float* W_out_d = (const float*)d_in[18];
    const float* b_out_d = (const float*)d_in[19];
    const float* W_out_p = (const float*)d_in[20];
    const float* b_out_p = (const float*)d_in[21];
    float* out = (float*)d_out;

    float *hd, *hp, *fs_dp, *fd_dp, *fs_pd, *fd_pd, *agg_p, *agg_d;
    float *el_dp, *er_dp, *el_pd, *er_pd, *s_p, *s_d, *ex_dp, *ex_pd;
    cudaGetSymbolAddress((void**)&hd,    g_hd);
    cudaGetSymbolAddress((void**)&hp,    g_hp);
    cudaGetSymbolAddress((void**)&fs_dp, g_fs_dp);
    cudaGetSymbolAddress((void**)&fd_dp, g_fd_dp);
    cudaGetSymbolAddress((void**)&fs_pd, g_fs_pd);
    cudaGetSymbolAddress((void**)&fd_pd, g_fd_pd);
    cudaGetSymbolAddress((void**)&agg_p, g_agg_p);
    cudaGetSymbolAddress((void**)&agg_d, g_agg_d);
    cudaGetSymbolAddress((void**)&el_dp, g_el_dp);
    cudaGetSymbolAddress((void**)&er_dp, g_er_dp);
    cudaGetSymbolAddress((void**)&el_pd, g_el_pd);
    cudaGetSymbolAddress((void**)&er_pd, g_er_pd);
    cudaGetSymbolAddress((void**)&s_p,   g_s_p);
    cudaGetSymbolAddress((void**)&s_d,   g_s_d);
    cudaGetSymbolAddress((void**)&ex_dp, g_ex_dp);
    cudaGetSymbolAddress((void**)&ex_pd, g_ex_pd);

    cudaFuncSetAttribute(gemm128, cudaFuncAttributeMaxDynamicSharedMemorySize, GEMM_SMEM);

    const int gb = (ND + 127) / 128;        // 782 (ND == NP)
    const int hdB = (int)(((size_t)ND * 32 + 255) / 256);
    const int iaB = (int)(((size_t)ND * 128 + 255) / 256);
    const int e1B = (EE + 255) / 256;
    const int e2B = (int)(((size_t)EE * 32 + 255) / 256);

    // input projections + relu
    gemm128<<<gb, 256, GEMM_SMEM>>>(x_drug, W_in_d, b_in_d, hd, ND, 1);
    gemm128<<<gb, 256, GEMM_SMEM>>>(x_prot, W_in_p, b_in_p, hp, NP, 1);
    // GAT feature projections (shared fc per etype, applied to src and dst sides)
    gemm128<<<gb, 256, GEMM_SMEM>>>(hd, W_dp, nullptr, fs_dp, ND, 0);
    gemm128<<<gb, 256, GEMM_SMEM>>>(hp, W_dp, nullptr, fd_dp, NP, 0);
    gemm128<<<gb, 256, GEMM_SMEM>>>(hp, W_pd, nullptr, fs_pd, NP, 0);
    gemm128<<<gb, 256, GEMM_SMEM>>>(hd, W_pd, nullptr, fd_pd, ND, 0);
    // attention logit halves
    headdot<<<hdB, 256>>>(fs_dp, al_dp, el_dp, ND);
    headdot<<<hdB, 256>>>(fd_dp, ar_dp, er_dp, NP);
    headdot<<<hdB, 256>>>(fs_pd, al_pd, el_pd, NP);
    headdot<<<hdB, 256>>>(fd_pd, ar_pd, er_pd, ND);
    // aggregation buffers (agg preloaded with GAT bias) + denominators
    init_agg<<<iaB, 256>>>(agg_p, bias_dp, s_p, NP);
    init_agg<<<iaB, 256>>>(agg_d, bias_pd, s_d, ND);
    // edge softmax + weighted aggregation
    edge_pass1<<<e1B, 256>>>(src_dp, dst_dp, el_dp, er_dp, ex_dp, s_p, EE);
    edge_pass1<<<e1B, 256>>>(src_pd, dst_pd, el_pd, er_pd, ex_pd, s_d, EE);
    edge_pass2<<<e2B, 256>>>(src_dp, dst_dp, ex_dp, s_p, fs_dp, agg_p, EE);
    edge_pass2<<<e2B, 256>>>(src_pd, dst_pd, ex_pd, s_d, fs_pd, agg_d, EE);
    // output projections: out_drug then out_prot
    gemm128<<<gb, 256, GEMM_SMEM>>>(agg_d, W_out_d, b_out_d, out, ND, 0);
    gemm128<<<gb, 256, GEMM_SMEM>>>(agg_p, W_out_p, b_out_p, out + (size_t)ND * 128, NP, 0);
}